// round 3
// baseline (speedup 1.0000x reference)
#include <cuda_runtime.h>
#include <cstddef>

#define CH   128
#define HH   96
#define WW   96
#define HW   9216          // 96*96
#define BATCH 16
#define NOUT 1000

// Scratch (device globals — no runtime allocation allowed)
__device__ float g_mixed[(size_t)BATCH * CH * HW];   // 75.5 MB
__device__ float g_x[(size_t)BATCH * CH * HW];       // 75.5 MB
__device__ float g_pool[BATCH * CH];

// ---------------------------------------------------------------------------
// Channel-mix GEMM: mixed[b,c,p] = sum_i lin[c,i] * xin[b,i,p]
// M=128 (out ch), N=9216 per batch (pixels), K = 64 or 128 (template).
// Block: 128 pixels x 128 channels, 256 threads, 8x8 microtile, BK=16,
// double-buffered smem with register staging (1 barrier per K-step).
// ---------------------------------------------------------------------------
template<int K>
__global__ void mix_gemm(const float* __restrict__ lin,
                         const float* __restrict__ xin,
                         float* __restrict__ out) {
    __shared__ float As[2][16][128];   // [buf][k][m]
    __shared__ float Bs[2][16][128];   // [buf][k][n]

    const int b     = blockIdx.y;
    const int pbase = blockIdx.x * 128;
    const int tid   = threadIdx.x;
    const int ty    = tid >> 4;     // 0..15  (channel group)
    const int tx    = tid & 15;     // 0..15  (pixel group)

    const float* xb = xin + (size_t)b * K * HW;

    // loader mapping (each thread: 2 float4 of A, 2 float4 of B per tile)
    const int am  = tid >> 2;          // 0..63   A row (and +64)
    const int akk = (tid & 3) * 4;     // 0,4,8,12
    const int bkk = tid >> 5;          // 0..7    B k (and +8)
    const int bn  = (tid & 31) * 4;    // pixel offset

    float4 a0, a1, b0, b1;

    auto load_gmem = [&](int k0) {
        a0 = *(const float4*)(lin + (size_t)am        * K + k0 + akk);
        a1 = *(const float4*)(lin + (size_t)(am + 64) * K + k0 + akk);
        b0 = *(const float4*)(xb + (size_t)(k0 + bkk)     * HW + pbase + bn);
        b1 = *(const float4*)(xb + (size_t)(k0 + bkk + 8) * HW + pbase + bn);
    };
    auto store_smem = [&](int buf) {
        As[buf][akk + 0][am] = a0.x; As[buf][akk + 1][am] = a0.y;
        As[buf][akk + 2][am] = a0.z; As[buf][akk + 3][am] = a0.w;
        As[buf][akk + 0][am + 64] = a1.x; As[buf][akk + 1][am + 64] = a1.y;
        As[buf][akk + 2][am + 64] = a1.z; As[buf][akk + 3][am + 64] = a1.w;
        *(float4*)&Bs[buf][bkk][bn]     = b0;
        *(float4*)&Bs[buf][bkk + 8][bn] = b1;
    };

    float acc[8][8];
#pragma unroll
    for (int i = 0; i < 8; i++)
#pragma unroll
        for (int j = 0; j < 8; j++) acc[i][j] = 0.f;

    constexpr int NT = K / 16;

    load_gmem(0);
    store_smem(0);
    __syncthreads();

#pragma unroll
    for (int t = 0; t < NT; t++) {
        if (t + 1 < NT) load_gmem((t + 1) * 16);
        const int cur = t & 1;
#pragma unroll
        for (int kk = 0; kk < 16; kk++) {
            float ra[8], rb[8];
#pragma unroll
            for (int i = 0; i < 8; i += 4) {
                float4 v = *(const float4*)&As[cur][kk][ty * 8 + i];
                ra[i] = v.x; ra[i+1] = v.y; ra[i+2] = v.z; ra[i+3] = v.w;
            }
#pragma unroll
            for (int j = 0; j < 8; j += 4) {
                float4 v = *(const float4*)&Bs[cur][kk][tx * 8 + j];
                rb[j] = v.x; rb[j+1] = v.y; rb[j+2] = v.z; rb[j+3] = v.w;
            }
#pragma unroll
            for (int i = 0; i < 8; i++)
#pragma unroll
                for (int j = 0; j < 8; j++)
                    acc[i][j] = fmaf(ra[i], rb[j], acc[i][j]);
        }
        if (t + 1 < NT) {
            store_smem((t + 1) & 1);
            __syncthreads();
        }
    }

    float* ob = out + (size_t)b * CH * HW + pbase;
#pragma unroll
    for (int i = 0; i < 8; i++) {
        int m = ty * 8 + i;
#pragma unroll
        for (int j0 = 0; j0 < 8; j0 += 4) {
            float4 v = make_float4(acc[i][j0], acc[i][j0+1], acc[i][j0+2], acc[i][j0+3]);
            *(float4*)(ob + (size_t)m * HW + tx * 8 + j0) = v;
        }
    }
}

// ---------------------------------------------------------------------------
// Affine bilinear sample of mixed (per-channel theta), times analytic box
// weight map (separable mask product — zero loads), plus optional residual.
// 4 pixels/thread along x; affine coords advance by exactly theta[0]/theta[3]
// per pixel, so per-pixel coordinate math is one fma per axis.
// grid: (HW/1024=9, 128 channels, 16 batch), 256 threads.
// ---------------------------------------------------------------------------
__global__ void sample_kernel(const float* __restrict__ mixed,
                              const float* __restrict__ geo,
                              const float* __restrict__ box,
                              const float* __restrict__ resid,
                              float* __restrict__ out) {
    const int c  = blockIdx.y;
    const int b  = blockIdx.z;
    const int t  = blockIdx.x * 256 + threadIdx.x;   // 0..2303
    const int p0 = t * 4;
    const int h  = p0 / WW;
    const int w0 = p0 - h * WW;

    const float gyc  = (h  + 0.5f) * (2.0f / HH) - 1.0f;
    const float gxc0 = (w0 + 0.5f) * (2.0f / WW) - 1.0f;

    const float* g = geo + c * 6;
    const float g0 = __ldg(g + 0), g1 = __ldg(g + 1), g2 = __ldg(g + 2);
    const float g3 = __ldg(g + 3), g4 = __ldg(g + 4), g5 = __ldg(g + 5);
    const float* bq = box + c * 6;
    const float q0 = __ldg(bq + 0), q1 = __ldg(bq + 1), q2 = __ldg(bq + 2);
    const float q3 = __ldg(bq + 3), q4 = __ldg(bq + 4), q5 = __ldg(bq + 5);

    // ix = gridx*48 + 47.5 ; d(ix)/d(w) = g0 exactly (step of gxc is 2/96)
    const float ix0  = (g0 * gxc0 + g1 * gyc + g2) * 48.f + 47.5f;
    const float iy0  = (g3 * gxc0 + g4 * gyc + g5) * 48.f + 47.5f;
    const float bix0 = (q0 * gxc0 + q1 * gyc + q2) * 48.f + 47.5f;
    const float biy0 = (q3 * gxc0 + q4 * gyc + q5) * 48.f + 47.5f;

    const float* plane = mixed + ((size_t)b * CH + c) * HW;
    const size_t idx   = ((size_t)b * CH + c) * HW + p0;

    float o[4];
#pragma unroll
    for (int j = 0; j < 4; j++) {
        const float fj = (float)j;
        // ---- geo sample (gather) ----
        float ix = fmaf(fj, g0, ix0);
        float iy = fmaf(fj, g3, iy0);
        float fx0 = floorf(ix), fy0 = floorf(iy);
        int   x0 = (int)fx0,  y0 = (int)fy0;
        float wx1 = ix - fx0, wy1 = iy - fy0;
        float wxa = ((unsigned)x0       < (unsigned)WW) ? (1.f - wx1) : 0.f;
        float wxb = ((unsigned)(x0 + 1) < (unsigned)WW) ? wx1         : 0.f;
        float wya = ((unsigned)y0       < (unsigned)HH) ? (1.f - wy1) : 0.f;
        float wyb = ((unsigned)(y0 + 1) < (unsigned)HH) ? wy1         : 0.f;
        int xc0 = min(max(x0, 0), WW - 1), xc1 = min(max(x0 + 1, 0), WW - 1);
        int yc0 = min(max(y0, 0), HH - 1), yc1 = min(max(y0 + 1, 0), HH - 1);
        const float* r0 = plane + yc0 * WW;
        const float* r1 = plane + yc1 * WW;
        float t00 = r0[xc0], t01 = r0[xc1], t10 = r1[xc0], t11 = r1[xc1];
        float s = wya * fmaf(wxa, t00, wxb * t01)
                + wyb * fmaf(wxa, t10, wxb * t11);

        // ---- box sample of ones: separable mask-weight product, no loads ----
        float bix = fmaf(fj, q0, bix0);
        float biy = fmaf(fj, q3, biy0);
        float bfx0 = floorf(bix), bfy0 = floorf(biy);
        int   bx0 = (int)bfx0,  by0 = (int)bfy0;
        float bwx1 = bix - bfx0, bwy1 = biy - bfy0;
        float sx = (((unsigned)bx0       < (unsigned)WW) ? (1.f - bwx1) : 0.f)
                 + (((unsigned)(bx0 + 1) < (unsigned)WW) ? bwx1         : 0.f);
        float sy = (((unsigned)by0       < (unsigned)HH) ? (1.f - bwy1) : 0.f)
                 + (((unsigned)(by0 + 1) < (unsigned)HH) ? bwy1         : 0.f);

        o[j] = s * (sx * sy);
    }

    if (resid) {
        float4 r = *(const float4*)(resid + idx);
        o[0] += r.x; o[1] += r.y; o[2] += r.z; o[3] += r.w;
    }
    float4 ov = make_float4(o[0], o[1], o[2], o[3]);
    *(float4*)(out + idx) = ov;
}

// ---------------------------------------------------------------------------
// Global average pool: one block per (b,c) plane.
// ---------------------------------------------------------------------------
__global__ void pool_kernel(const float* __restrict__ feat,
                            float* __restrict__ pooled) {
    const int bc = blockIdx.x;             // 0..2047
    const float* plane = feat + (size_t)bc * HW;
    float s = 0.f;
    for (int i = threadIdx.x; i < HW / 4; i += 256) {
        float4 v = *(const float4*)(plane + i * 4);
        s += (v.x + v.y) + (v.z + v.w);
    }
    for (int o = 16; o > 0; o >>= 1) s += __shfl_down_sync(0xffffffffu, s, o);
    __shared__ float sm[8];
    if ((threadIdx.x & 31) == 0) sm[threadIdx.x >> 5] = s;
    __syncthreads();
    if (threadIdx.x == 0) {
        float tacc = 0.f;
        for (int i = 0; i < 8; i++) tacc += sm[i];
        pooled[bc] = tacc * (1.0f / HW);
    }
}

// ---------------------------------------------------------------------------
// Dense head: logits[b,o] = pooled[b,:] . dense_w[o,:] + dense_b[o]
// ---------------------------------------------------------------------------
__global__ void dense_kernel(const float* __restrict__ pooled,
                             const float* __restrict__ dw,
                             const float* __restrict__ db,
                             float* __restrict__ logits) {
    int gid = blockIdx.x * 256 + threadIdx.x;
    if (gid >= BATCH * NOUT) return;
    int o = gid % NOUT;
    int b = gid / NOUT;
    const float* pr = pooled + b * CH;
    const float* wr = dw + (size_t)o * CH;
    float s = 0.f;
#pragma unroll 16
    for (int c = 0; c < CH; c++) s = fmaf(pr[c], wr[c], s);
    logits[gid] = s + db[o];
}

// ---------------------------------------------------------------------------
extern "C" void kernel_launch(void* const* d_in, const int* in_sizes, int n_in,
                              void* d_out, int out_size) {
    const float* x       = (const float*)d_in[0];  // [16,64,96,96]
    const float* in_geo  = (const float*)d_in[1];  // [128,2,3]
    const float* in_box  = (const float*)d_in[2];
    const float* in_lin  = (const float*)d_in[3];  // [128,64]
    const float* lay_geo = (const float*)d_in[4];  // [4,128,2,3]
    const float* lay_box = (const float*)d_in[5];
    const float* lay_lin = (const float*)d_in[6];  // [4,128,128]
    const float* dense_w = (const float*)d_in[7];  // [1000,128]
    const float* dense_b = (const float*)d_in[8];  // [1000]

    float* out    = (float*)d_out;
    float* logits = out;                 // [16,1000]
    float* feat   = out + BATCH * NOUT;  // [16,128,96,96]

    float *mixed_p, *x_p, *pool_p;
    cudaGetSymbolAddress((void**)&mixed_p, g_mixed);
    cudaGetSymbolAddress((void**)&x_p,     g_x);
    cudaGetSymbolAddress((void**)&pool_p,  g_pool);

    dim3 ggrid(HW / 128, BATCH);          // (72, 16)
    dim3 sgrid(HW / 1024, CH, BATCH);     // (9, 128, 16)

    // input layer (K=64, no residual)
    mix_gemm<64><<<ggrid, 256>>>(in_lin, x, mixed_p);
    sample_kernel<<<sgrid, 256>>>(mixed_p, in_geo, in_box, nullptr, x_p);

    // 4 residual layers (K=128)
    for (int i = 0; i < 4; i++) {
        mix_gemm<128><<<ggrid, 256>>>(lay_lin + (size_t)i * CH * CH, x_p, mixed_p);
        float* dst = (i == 3) ? feat : x_p;
        sample_kernel<<<sgrid, 256>>>(mixed_p, lay_geo + (size_t)i * CH * 6,
                                      lay_box + (size_t)i * CH * 6, x_p, dst);
    }

    pool_kernel<<<BATCH * CH, 256>>>(feat, pool_p);
    dense_kernel<<<(BATCH * NOUT + 255) / 256, 256>>>(pool_p, dense_w, dense_b, logits);
}

// round 8
// speedup vs baseline: 1.1587x; 1.1587x over previous
#include <cuda_runtime.h>
#include <cstdint>
#include <cstddef>

#define CH   128
#define HH   96
#define WW   96
#define HW   9216          // 96*96
#define BATCH 16
#define NOUT 1000

// Scratch (device globals — no runtime allocation allowed)
__device__ float g_mixed[(size_t)BATCH * CH * HW];   // 75.5 MB
__device__ float g_x[(size_t)BATCH * CH * HW];       // 75.5 MB
__device__ float g_pool[BATCH * CH];

// ---------------------------------------------------------------------------
// Packed f32x2 helpers (PTX fma.rn.f32x2 — sm_100-family, ptxas never
// auto-generates it from C++; must be inline PTX).
// ---------------------------------------------------------------------------
__device__ __forceinline__ unsigned long long pack_dup(float a) {
    unsigned long long r;
    asm("mov.b64 %0, {%1, %1};" : "=l"(r) : "r"(__float_as_uint(a)));
    return r;
}
__device__ __forceinline__ void fma2(unsigned long long& acc,
                                     unsigned long long a,
                                     unsigned long long b) {
    asm("fma.rn.f32x2 %0, %1, %2, %0;" : "+l"(acc) : "l"(a), "l"(b));
}

// ---------------------------------------------------------------------------
// Channel-mix GEMM: mixed[b,c,p] = sum_i lin[c,i] * xin[b,i,p]
// M=128 (out ch), N=9216 per batch (pixels), K = 64 or 128.
// Block: 128 pixels x 128 channels, 256 threads, 8x8 microtile, BK=16.
// Inner product uses packed fma.rn.f32x2 (2 MACs / issue).
// ---------------------------------------------------------------------------
__global__ void mix_gemm(const float* __restrict__ lin,
                         const float* __restrict__ xin,
                         float* __restrict__ out, int K) {
    __shared__ float As[16][128];   // [k][m]  (lin transposed)
    __shared__ float Bs[16][128];   // [k][n]

    const int b     = blockIdx.y;
    const int pbase = blockIdx.x * 128;
    const int tid   = threadIdx.x;
    const int ty    = tid >> 4;     // 0..15  (channel group)
    const int tx    = tid & 15;     // 0..15  (pixel group)

    const float* xb = xin + (size_t)b * K * HW;

    // acc[i][j] = packed pair for pixels (2j, 2j+1) of channel row i
    unsigned long long acc[8][4];
#pragma unroll
    for (int i = 0; i < 8; i++)
#pragma unroll
        for (int j = 0; j < 4; j++) acc[i][j] = 0ull;

    for (int k0 = 0; k0 < K; k0 += 16) {
        // A tile: 128 rows x 16 k  = 512 float4
#pragma unroll
        for (int r = 0; r < 2; r++) {
            int li = tid + r * 256;           // 0..511
            int m  = li >> 2;                 // 0..127
            int kk = (li & 3) * 4;            // 0,4,8,12
            float4 a = *(const float4*)(lin + (size_t)m * K + k0 + kk);
            As[kk + 0][m] = a.x; As[kk + 1][m] = a.y;
            As[kk + 2][m] = a.z; As[kk + 3][m] = a.w;
        }
        // B tile: 16 k x 128 pixels = 512 float4
#pragma unroll
        for (int r = 0; r < 2; r++) {
            int li = tid + r * 256;
            int kk = li >> 5;                 // 0..15
            int n4 = li & 31;                 // 0..31
            *(float4*)&Bs[kk][n4 * 4] =
                *(const float4*)(xb + (size_t)(k0 + kk) * HW + pbase + n4 * 4);
        }
        __syncthreads();

#pragma unroll
        for (int kk = 0; kk < 16; kk++) {
            // B fragment: 8 pixels = 4 packed pairs (bit layout already f32x2)
            ulonglong2 bv0 = *(const ulonglong2*)&Bs[kk][tx * 8];
            ulonglong2 bv1 = *(const ulonglong2*)&Bs[kk][tx * 8 + 4];
            unsigned long long rb[4] = {bv0.x, bv0.y, bv1.x, bv1.y};
            float4 a0 = *(const float4*)&As[kk][ty * 8];
            float4 a1 = *(const float4*)&As[kk][ty * 8 + 4];
            float ra[8] = {a0.x, a0.y, a0.z, a0.w, a1.x, a1.y, a1.z, a1.w};
#pragma unroll
            for (int i = 0; i < 8; i++) {
                unsigned long long ra2 = pack_dup(ra[i]);
#pragma unroll
                for (int j = 0; j < 4; j++) fma2(acc[i][j], ra2, rb[j]);
            }
        }
        __syncthreads();
    }

    float* ob = out + (size_t)b * CH * HW + pbase;
#pragma unroll
    for (int i = 0; i < 8; i++) {
        int m = ty * 8 + i;
#pragma unroll
        for (int j0 = 0; j0 < 4; j0 += 2) {
            ulonglong2 v = make_ulonglong2(acc[i][j0], acc[i][j0 + 1]);
            *(ulonglong2*)(ob + (size_t)m * HW + tx * 8 + j0 * 2) = v;
        }
    }
}

// ---------------------------------------------------------------------------
// Sample: 4 pixels/thread along y (warp = 32 consecutive x -> coalesced taps).
// Incremental affine: per +1 row, ix += g1, iy += g4 (exact).
// Box map of ones is analytic (separable mask product, zero loads).
// grid (3, 3, CH*BATCH), 256 threads.
// ---------------------------------------------------------------------------
__global__ void sample_kernel(const float* __restrict__ mixed,
                              const float* __restrict__ geo,
                              const float* __restrict__ box,
                              const float* __restrict__ resid,
                              float* __restrict__ out) {
    const int zc   = blockIdx.z;           // b*CH + c
    const int c    = zc & (CH - 1);
    const int lane = threadIdx.x & 31;
    const int warp = threadIdx.x >> 5;
    const int w    = blockIdx.x * 32 + lane;
    const int h0   = blockIdx.y * 32 + warp * 4;

    const float gxc = (w  + 0.5f) * (2.0f / WW) - 1.0f;
    const float gyc = (h0 + 0.5f) * (2.0f / HH) - 1.0f;

    const float* g = geo + c * 6;
    const float g0 = __ldg(g + 0), g1 = __ldg(g + 1), g2 = __ldg(g + 2);
    const float g3 = __ldg(g + 3), g4 = __ldg(g + 4), g5 = __ldg(g + 5);
    const float* bq = box + c * 6;
    const float q0 = __ldg(bq + 0), q1 = __ldg(bq + 1), q2 = __ldg(bq + 2);
    const float q3 = __ldg(bq + 3), q4 = __ldg(bq + 4), q5 = __ldg(bq + 5);

    float ix  = (g0 * gxc + g1 * gyc + g2) * 48.f + 47.5f;
    float iy  = (g3 * gxc + g4 * gyc + g5) * 48.f + 47.5f;
    float bix = (q0 * gxc + q1 * gyc + q2) * 48.f + 47.5f;
    float biy = (q3 * gxc + q4 * gyc + q5) * 48.f + 47.5f;

    const float* plane = mixed + (size_t)zc * HW;
    const size_t base  = (size_t)zc * HW + (size_t)h0 * WW + w;
    const bool   has_r = (resid != nullptr);

#pragma unroll
    for (int k = 0; k < 4; k++) {
        // ---- geo sample (gather) ----
        float fx0 = floorf(ix), fy0 = floorf(iy);
        int   x0 = (int)fx0,  y0 = (int)fy0;
        float wx1 = ix - fx0, wy1 = iy - fy0;
        float wxa = ((unsigned)x0       < (unsigned)WW) ? (1.f - wx1) : 0.f;
        float wxb = ((unsigned)(x0 + 1) < (unsigned)WW) ? wx1         : 0.f;
        float wya = ((unsigned)y0       < (unsigned)HH) ? (1.f - wy1) : 0.f;
        float wyb = ((unsigned)(y0 + 1) < (unsigned)HH) ? wy1         : 0.f;
        int xc0 = min(max(x0, 0), WW - 1), xc1 = min(max(x0 + 1, 0), WW - 1);
        int yc0 = min(max(y0, 0), HH - 1), yc1 = min(max(y0 + 1, 0), HH - 1);
        const float* r0 = plane + yc0 * WW;
        const float* r1 = plane + yc1 * WW;
        float s = wya * fmaf(wxa, r0[xc0], wxb * r0[xc1])
                + wyb * fmaf(wxa, r1[xc0], wxb * r1[xc1]);

        // ---- box sample of ones: separable mask product, no loads ----
        float bfx = floorf(bix), bfy = floorf(biy);
        int   bx0 = (int)bfx,  by0 = (int)bfy;
        float bwx1 = bix - bfx, bwy1 = biy - bfy;
        float sx = (((unsigned)bx0       < (unsigned)WW) ? (1.f - bwx1) : 0.f)
                 + (((unsigned)(bx0 + 1) < (unsigned)WW) ? bwx1         : 0.f);
        float sy = (((unsigned)by0       < (unsigned)HH) ? (1.f - bwy1) : 0.f)
                 + (((unsigned)(by0 + 1) < (unsigned)HH) ? bwy1         : 0.f);

        float v = s * (sx * sy);
        if (has_r) v += resid[base + (size_t)k * WW];
        out[base + (size_t)k * WW] = v;

        ix += g1; iy += g4; bix += q1; biy += q4;
    }
}

// ---------------------------------------------------------------------------
// Global average pool: one block per (b,c) plane.
// ---------------------------------------------------------------------------
__global__ void pool_kernel(const float* __restrict__ feat,
                            float* __restrict__ pooled) {
    const int bc = blockIdx.x;             // 0..2047
    const float* plane = feat + (size_t)bc * HW;
    float s = 0.f;
    for (int i = threadIdx.x; i < HW / 4; i += 256) {
        float4 v = *(const float4*)(plane + i * 4);
        s += (v.x + v.y) + (v.z + v.w);
    }
    for (int o = 16; o > 0; o >>= 1) s += __shfl_down_sync(0xffffffffu, s, o);
    __shared__ float sm[8];
    if ((threadIdx.x & 31) == 0) sm[threadIdx.x >> 5] = s;
    __syncthreads();
    if (threadIdx.x == 0) {
        float t = 0.f;
        for (int i = 0; i < 8; i++) t += sm[i];
        pooled[bc] = t * (1.0f / HW);
    }
}

// ---------------------------------------------------------------------------
// Dense head: logits[b,o] = pooled[b,:] . dense_w[o,:] + dense_b[o]
// ---------------------------------------------------------------------------
__global__ void dense_kernel(const float* __restrict__ pooled,
                             const float* __restrict__ dw,
                             const float* __restrict__ db,
                             float* __restrict__ logits) {
    int gid = blockIdx.x * 256 + threadIdx.x;
    if (gid >= BATCH * NOUT) return;
    int o = gid % NOUT;
    int b = gid / NOUT;
    const float* pr = pooled + b * CH;
    const float* wr = dw + (size_t)o * CH;
    float s = 0.f;
#pragma unroll 16
    for (int c = 0; c < CH; c++) s = fmaf(pr[c], wr[c], s);
    logits[gid] = s + db[o];
}

// ---------------------------------------------------------------------------
extern "C" void kernel_launch(void* const* d_in, const int* in_sizes, int n_in,
                              void* d_out, int out_size) {
    const float* x       = (const float*)d_in[0];  // [16,64,96,96]
    const float* in_geo  = (const float*)d_in[1];  // [128,2,3]
    const float* in_box  = (const float*)d_in[2];
    const float* in_lin  = (const float*)d_in[3];  // [128,64]
    const float* lay_geo = (const float*)d_in[4];  // [4,128,2,3]
    const float* lay_box = (const float*)d_in[5];
    const float* lay_lin = (const float*)d_in[6];  // [4,128,128]
    const float* dense_w = (const float*)d_in[7];  // [1000,128]
    const float* dense_b = (const float*)d_in[8];  // [1000]

    float* out    = (float*)d_out;
    float* logits = out;                 // [16,1000]
    float* feat   = out + BATCH * NOUT;  // [16,128,96,96]

    float *mixed_p, *x_p, *pool_p;
    cudaGetSymbolAddress((void**)&mixed_p, g_mixed);
    cudaGetSymbolAddress((void**)&x_p,     g_x);
    cudaGetSymbolAddress((void**)&pool_p,  g_pool);

    dim3 ggrid(HW / 128, BATCH);          // (72, 16)
    dim3 sgrid(3, 3, CH * BATCH);         // (3, 3, 2048)

    // input layer (K=64, no residual)
    mix_gemm<<<ggrid, 256>>>(in_lin, x, mixed_p, 64);
    sample_kernel<<<sgrid, 256>>>(mixed_p, in_geo, in_box, nullptr, x_p);

    // 4 residual layers (K=128)
    for (int i = 0; i < 4; i++) {
        mix_gemm<<<ggrid, 256>>>(lay_lin + (size_t)i * CH * CH, x_p, mixed_p, 128);
        float* dst = (i == 3) ? feat : x_p;
        sample_kernel<<<sgrid, 256>>>(mixed_p, lay_geo + (size_t)i * CH * 6,
                                      lay_box + (size_t)i * CH * 6, x_p, dst);
    }

    pool_kernel<<<BATCH * CH, 256>>>(feat, pool_p);
    dense_kernel<<<(BATCH * NOUT + 255) / 256, 256>>>(pool_p, dense_w, dense_b, logits);
}

// round 9
// speedup vs baseline: 1.9139x; 1.6518x over previous
#include <cuda_runtime.h>
#include <cuda_bf16.h>
#include <cstdint>
#include <cstddef>

#define CH   128
#define HH   96
#define WW   96
#define HW   9216          // 96*96
#define BATCH 16
#define NOUT 1000

// ---------------------------------------------------------------------------
// Scratch (device globals — no runtime allocation allowed)
// ---------------------------------------------------------------------------
__device__ float g_mixed[(size_t)BATCH * CH * HW];      // 75.5 MB
__device__ float g_x[(size_t)BATCH * CH * HW];          // 75.5 MB
__device__ float g_pool[BATCH * CH];
// bf16 pair-packed B operand: row r = b*K2 + k2 holds u32(bf16 ch 2k2, ch 2k2+1)
__device__ unsigned int g_pbh[(size_t)BATCH * 64 * HW]; // 37.75 MB
__device__ unsigned int g_pbl[(size_t)BATCH * 64 * HW]; // 37.75 MB
// A fragments in mma register order: [slot][kstep(8)][mtile(8)][lane(32)] uint4
__device__ uint4 g_afh[5 * 8 * 8 * 32];
__device__ uint4 g_afl[5 * 8 * 8 * 32];

// ---------------------------------------------------------------------------
__device__ __forceinline__ unsigned short bfbits(float x) {
    return __bfloat16_as_ushort(__float2bfloat16_rn(x));
}
__device__ __forceinline__ float bfval(float x) {
    return __bfloat162float(__float2bfloat16_rn(x));
}
__device__ __forceinline__ unsigned int pack2(unsigned short lo, unsigned short hi) {
    return (unsigned int)lo | ((unsigned int)hi << 16);
}
// mma.sync m16n8k16 row.col f32.bf16.bf16.f32 (sm_80+ PTX, valid on compute_103)
__device__ __forceinline__ void mma_bf16(float* d, uint4 a,
                                         unsigned int b0, unsigned int b1) {
    asm volatile(
        "mma.sync.aligned.m16n8k16.row.col.f32.bf16.bf16.f32 "
        "{%0,%1,%2,%3}, {%4,%5,%6,%7}, {%8,%9}, {%0,%1,%2,%3};"
        : "+f"(d[0]), "+f"(d[1]), "+f"(d[2]), "+f"(d[3])
        : "r"(a.x), "r"(a.y), "r"(a.z), "r"(a.w), "r"(b0), "r"(b1));
}

// ---------------------------------------------------------------------------
// prep_A: pack lin [CH x K] fp32 into hi/lo bf16 mma A-fragments (reg order:
// a0=(m,k0..k0+1) a1=(m+8,..) a2=(m,k0+8..9) a3=(m+8,k0+8..9)).
// ---------------------------------------------------------------------------
__global__ void prep_A(const float* __restrict__ lin, int K, int slot) {
    int t = blockIdx.x * 256 + threadIdx.x;
    int n = (K / 16) * 8 * 32;
    if (t >= n) return;
    int lane  = t & 31;
    int mtile = (t >> 5) & 7;
    int ks    = t >> 8;
    int m0 = mtile * 16 + (lane >> 2);
    int k0 = ks * 16 + (lane & 3) * 2;

    float a00 = lin[(size_t)m0 * K + k0],       a01 = lin[(size_t)m0 * K + k0 + 1];
    float a10 = lin[(size_t)(m0 + 8) * K + k0], a11 = lin[(size_t)(m0 + 8) * K + k0 + 1];
    float a02 = lin[(size_t)m0 * K + k0 + 8],   a03 = lin[(size_t)m0 * K + k0 + 9];
    float a12 = lin[(size_t)(m0 + 8) * K + k0 + 8], a13 = lin[(size_t)(m0 + 8) * K + k0 + 9];

    uint4 h, l;
    h.x = pack2(bfbits(a00), bfbits(a01));
    h.y = pack2(bfbits(a10), bfbits(a11));
    h.z = pack2(bfbits(a02), bfbits(a03));
    h.w = pack2(bfbits(a12), bfbits(a13));
    l.x = pack2(bfbits(a00 - bfval(a00)), bfbits(a01 - bfval(a01)));
    l.y = pack2(bfbits(a10 - bfval(a10)), bfbits(a11 - bfval(a11)));
    l.z = pack2(bfbits(a02 - bfval(a02)), bfbits(a03 - bfval(a03)));
    l.w = pack2(bfbits(a12 - bfval(a12)), bfbits(a13 - bfval(a13)));

    int off = ((slot * 8 + ks) * 8 + mtile) * 32 + lane;
    g_afh[off] = h;
    g_afl[off] = l;
}

// ---------------------------------------------------------------------------
// convert_in: x fp32 [16,64,HW] -> pair-packed bf16 hi/lo (K2=32 rows/batch)
// ---------------------------------------------------------------------------
__global__ void convert_in(const float* __restrict__ x,
                           unsigned int* __restrict__ pbh,
                           unsigned int* __restrict__ pbl) {
    size_t t = (size_t)blockIdx.x * 256 + threadIdx.x;  // 16*32*2304 threads
    int p4 = (int)(t % 2304);
    int k2 = (int)((t / 2304) % 32);
    int b  = (int)(t / (2304 * 32));
    const float4 v0 = *(const float4*)(x + ((size_t)b * 64 + 2 * k2)     * HW + p4 * 4);
    const float4 v1 = *(const float4*)(x + ((size_t)b * 64 + 2 * k2 + 1) * HW + p4 * 4);
    uint4 h, l;
    h.x = pack2(bfbits(v0.x), bfbits(v1.x));
    h.y = pack2(bfbits(v0.y), bfbits(v1.y));
    h.z = pack2(bfbits(v0.z), bfbits(v1.z));
    h.w = pack2(bfbits(v0.w), bfbits(v1.w));
    l.x = pack2(bfbits(v0.x - bfval(v0.x)), bfbits(v1.x - bfval(v1.x)));
    l.y = pack2(bfbits(v0.y - bfval(v0.y)), bfbits(v1.y - bfval(v1.y)));
    l.z = pack2(bfbits(v0.z - bfval(v0.z)), bfbits(v1.z - bfval(v1.z)));
    l.w = pack2(bfbits(v0.w - bfval(v0.w)), bfbits(v1.w - bfval(v1.w)));
    size_t o = ((size_t)b * 32 + k2) * HW + (size_t)p4 * 4;
    *(uint4*)(pbh + o) = h;
    *(uint4*)(pbl + o) = l;
}

// ---------------------------------------------------------------------------
// Tensor GEMM: mixed[b,c,p] = sum_i lin[c,i] * xin[b,i,p]  via bf16 hi/lo
// split (Ah*Bh + Ah*Bl + Al*Bh). Block: 128ch x 128px, 8 warps (2m x 4n),
// full-K B tile in smem (pitch 136 u32 -> conflict-free fragment LDS).
// ---------------------------------------------------------------------------
#define BPITCH 136
template<int K>
__global__ __launch_bounds__(256, 2)
void mix_gemm_mma(const unsigned int* __restrict__ pbh,
                  const unsigned int* __restrict__ pbl,
                  float* __restrict__ out, int slot) {
    constexpr int K2 = K / 2;
    constexpr int KS = K / 16;
    extern __shared__ unsigned int smb[];
    unsigned int* Bh = smb;
    unsigned int* Bl = smb + K2 * BPITCH;

    const int b     = blockIdx.y;
    const int pbase = blockIdx.x * 128;
    const int tid   = threadIdx.x;
    const int lane  = tid & 31;
    const int warp  = tid >> 5;
    const int wm    = warp >> 2;   // 0..1
    const int wn    = warp & 3;    // 0..3

    // load B tiles (coalesced u32 rows)
    {
        const unsigned int* gh = pbh + ((size_t)b * K2) * HW + pbase;
        const unsigned int* gl = pbl + ((size_t)b * K2) * HW + pbase;
        for (int i = tid; i < K2 * 128; i += 256) {
            int r = i >> 7, c2 = i & 127;
            Bh[r * BPITCH + c2] = gh[(size_t)r * HW + c2];
            Bl[r * BPITCH + c2] = gl[(size_t)r * HW + c2];
        }
    }
    __syncthreads();

    float acc[4][4][4];
#pragma unroll
    for (int t = 0; t < 4; t++)
#pragma unroll
        for (int u = 0; u < 4; u++)
#pragma unroll
            for (int r = 0; r < 4; r++) acc[t][u][r] = 0.f;

    const uint4* afh = g_afh + (size_t)slot * 8 * 8 * 32;
    const uint4* afl = g_afl + (size_t)slot * 8 * 8 * 32;

#pragma unroll
    for (int ks = 0; ks < KS; ks++) {
        unsigned int bh0[4], bh1[4], bl0[4], bl1[4];
        const int r0 = (ks * 8 + (lane & 3)) * BPITCH;
        const int r1 = r0 + 4 * BPITCH;
#pragma unroll
        for (int u = 0; u < 4; u++) {
            int n = wn * 32 + u * 8 + (lane >> 2);
            bh0[u] = Bh[r0 + n]; bh1[u] = Bh[r1 + n];
            bl0[u] = Bl[r0 + n]; bl1[u] = Bl[r1 + n];
        }
#pragma unroll
        for (int t = 0; t < 4; t++) {
            uint4 ah = afh[(ks * 8 + wm * 4 + t) * 32 + lane];
            uint4 al = afl[(ks * 8 + wm * 4 + t) * 32 + lane];
#pragma unroll
            for (int u = 0; u < 4; u++) {
                mma_bf16(acc[t][u], ah, bh0[u], bh1[u]);
                mma_bf16(acc[t][u], ah, bl0[u], bl1[u]);
                mma_bf16(acc[t][u], al, bh0[u], bh1[u]);
            }
        }
    }

    float* ob = out + (size_t)b * CH * HW + pbase;
#pragma unroll
    for (int t = 0; t < 4; t++) {
        int m0 = wm * 64 + t * 16 + (lane >> 2);
#pragma unroll
        for (int u = 0; u < 4; u++) {
            int n0 = wn * 32 + u * 8 + (lane & 3) * 2;
            *(float2*)(ob + (size_t)m0 * HW + n0)       = make_float2(acc[t][u][0], acc[t][u][1]);
            *(float2*)(ob + (size_t)(m0 + 8) * HW + n0) = make_float2(acc[t][u][2], acc[t][u][3]);
        }
    }
}

// ---------------------------------------------------------------------------
// Sample (R1 measured-best structure) + optional bf16 pair-packed hi/lo
// output for next layer's GEMM B operand.
// grid: (36, 128 channels, 16 batch), 256 threads (one output pixel each).
// ---------------------------------------------------------------------------
__global__ void sample_kernel(const float* __restrict__ mixed,
                              const float* __restrict__ geo,
                              const float* __restrict__ box,
                              const float* __restrict__ resid,
                              float* __restrict__ out,
                              unsigned int* __restrict__ pbh,
                              unsigned int* __restrict__ pbl) {
    const int c = blockIdx.y;
    const int b = blockIdx.z;
    const int p = blockIdx.x * 256 + threadIdx.x;
    const int h = p / WW;
    const int w = p - h * WW;

    const float gxc = (w + 0.5f) * (2.0f / WW) - 1.0f;
    const float gyc = (h + 0.5f) * (2.0f / HH) - 1.0f;

    const float* g = geo + c * 6;
    float gridx = g[0] * gxc + g[1] * gyc + g[2];
    float gridy = g[3] * gxc + g[4] * gyc + g[5];
    float ix = ((gridx + 1.0f) * WW - 1.0f) * 0.5f;
    float iy = ((gridy + 1.0f) * HH - 1.0f) * 0.5f;
    float fx0 = floorf(ix), fy0 = floorf(iy);
    int   x0 = (int)fx0, y0 = (int)fy0;
    float wx1 = ix - fx0, wy1 = iy - fy0;
    float wx0 = 1.0f - wx1, wy0 = 1.0f - wy1;

    const float* plane = mixed + ((size_t)b * CH + c) * HW;
    auto tap = [&](int yi, int xi, float wt) -> float {
        bool v = (xi >= 0) & (xi < WW) & (yi >= 0) & (yi < HH);
        int xc = min(max(xi, 0), WW - 1);
        int yc = min(max(yi, 0), HH - 1);
        return v ? plane[yc * WW + xc] * wt : 0.0f;
    };
    float s = tap(y0,     x0,     wy0 * wx0)
            + tap(y0,     x0 + 1, wy0 * wx1)
            + tap(y0 + 1, x0,     wy1 * wx0)
            + tap(y0 + 1, x0 + 1, wy1 * wx1);

    const float* bx = box + c * 6;
    float bgx = bx[0] * gxc + bx[1] * gyc + bx[2];
    float bgy = bx[3] * gxc + bx[4] * gyc + bx[5];
    float bix = ((bgx + 1.0f) * WW - 1.0f) * 0.5f;
    float biy = ((bgy + 1.0f) * HH - 1.0f) * 0.5f;
    float bfx0 = floorf(bix), bfy0 = floorf(biy);
    int   bx0 = (int)bfx0, by0 = (int)bfy0;
    float bwx1 = bix - bfx0, bwy1 = biy - bfy0;
    float bwx0 = 1.0f - bwx1, bwy0 = 1.0f - bwy1;

    auto vmask = [](int yi, int xi) -> float {
        return ((xi >= 0) & (xi < WW) & (yi >= 0) & (yi < HH)) ? 1.0f : 0.0f;
    };
    float bval = vmask(by0,     bx0)     * bwy0 * bwx0
               + vmask(by0,     bx0 + 1) * bwy0 * bwx1
               + vmask(by0 + 1, bx0)     * bwy1 * bwx0
               + vmask(by0 + 1, bx0 + 1) * bwy1 * bwx1;

    const size_t idx = ((size_t)b * CH + c) * HW + p;
    float v = s * bval;
    if (resid) v += resid[idx];
    out[idx] = v;

    if (pbh) {
        unsigned short hb = bfbits(v);
        unsigned short lb = bfbits(v - __bfloat162float(__ushort_as_bfloat16(hb)));
        size_t hwi = (((size_t)b * 64 + (c >> 1)) * HW + p) * 2 + (c & 1);
        ((unsigned short*)pbh)[hwi] = hb;
        ((unsigned short*)pbl)[hwi] = lb;
    }
}

// ---------------------------------------------------------------------------
__global__ void pool_kernel(const float* __restrict__ feat,
                            float* __restrict__ pooled) {
    const int bc = blockIdx.x;
    const float* plane = feat + (size_t)bc * HW;
    float s = 0.f;
    for (int i = threadIdx.x; i < HW / 4; i += 256) {
        float4 v = *(const float4*)(plane + i * 4);
        s += (v.x + v.y) + (v.z + v.w);
    }
    for (int o = 16; o > 0; o >>= 1) s += __shfl_down_sync(0xffffffffu, s, o);
    __shared__ float sm[8];
    if ((threadIdx.x & 31) == 0) sm[threadIdx.x >> 5] = s;
    __syncthreads();
    if (threadIdx.x == 0) {
        float t = 0.f;
        for (int i = 0; i < 8; i++) t += sm[i];
        pooled[bc] = t * (1.0f / HW);
    }
}

__global__ void dense_kernel(const float* __restrict__ pooled,
                             const float* __restrict__ dw,
                             const float* __restrict__ db,
                             float* __restrict__ logits) {
    int gid = blockIdx.x * 256 + threadIdx.x;
    if (gid >= BATCH * NOUT) return;
    int o = gid % NOUT;
    int b = gid / NOUT;
    const float* pr = pooled + b * CH;
    const float* wr = dw + (size_t)o * CH;
    float s = 0.f;
#pragma unroll 16
    for (int c = 0; c < CH; c++) s = fmaf(pr[c], wr[c], s);
    logits[gid] = s + db[o];
}

// ---------------------------------------------------------------------------
extern "C" void kernel_launch(void* const* d_in, const int* in_sizes, int n_in,
                              void* d_out, int out_size) {
    const float* x       = (const float*)d_in[0];
    const float* in_geo  = (const float*)d_in[1];
    const float* in_box  = (const float*)d_in[2];
    const float* in_lin  = (const float*)d_in[3];
    const float* lay_geo = (const float*)d_in[4];
    const float* lay_box = (const float*)d_in[5];
    const float* lay_lin = (const float*)d_in[6];
    const float* dense_w = (const float*)d_in[7];
    const float* dense_b = (const float*)d_in[8];

    float* out    = (float*)d_out;
    float* logits = out;
    float* feat   = out + BATCH * NOUT;

    float *mixed_p, *x_p, *pool_p;
    unsigned int *pbh_p, *pbl_p;
    cudaGetSymbolAddress((void**)&mixed_p, g_mixed);
    cudaGetSymbolAddress((void**)&x_p,     g_x);
    cudaGetSymbolAddress((void**)&pool_p,  g_pool);
    cudaGetSymbolAddress((void**)&pbh_p,   g_pbh);
    cudaGetSymbolAddress((void**)&pbl_p,   g_pbl);

    const int smem64  = 2 * 32 * BPITCH * 4;   // 34816
    const int smem128 = 2 * 64 * BPITCH * 4;   // 69632
    static bool attr_done = false;
    if (!attr_done) {
        cudaFuncSetAttribute(mix_gemm_mma<64>,  cudaFuncAttributeMaxDynamicSharedMemorySize, smem64);
        cudaFuncSetAttribute(mix_gemm_mma<128>, cudaFuncAttributeMaxDynamicSharedMemorySize, smem128);
        attr_done = true;
    }

    // A fragment prep (5 tiny launches)
    prep_A<<<(4 * 8 * 32 + 255) / 256, 256>>>(in_lin, 64, 0);
    for (int i = 0; i < 4; i++)
        prep_A<<<(8 * 8 * 32 + 255) / 256, 256>>>(lay_lin + (size_t)i * CH * CH, 128, i + 1);
    // input conversion to packed bf16 hi/lo
    convert_in<<<(BATCH * 32 * 2304 + 255) / 256, 256>>>(x, pbh_p, pbl_p);

    dim3 ggrid(HW / 128, BATCH);          // (72, 16)
    dim3 sgrid(HW / 256, CH, BATCH);      // (36, 128, 16)

    // input layer (K=64, no residual); sample also emits bf16 for next GEMM
    mix_gemm_mma<64><<<ggrid, 256, smem64>>>(pbh_p, pbl_p, mixed_p, 0);
    sample_kernel<<<sgrid, 256>>>(mixed_p, in_geo, in_box, nullptr, x_p, pbh_p, pbl_p);

    // 4 residual layers (K=128)
    for (int i = 0; i < 4; i++) {
        mix_gemm_mma<128><<<ggrid, 256, smem128>>>(pbh_p, pbl_p, mixed_p, i + 1);
        float* dst = (i == 3) ? feat : x_p;
        unsigned int* ph = (i == 3) ? nullptr : pbh_p;
        unsigned int* pl = (i == 3) ? nullptr : pbl_p;
        sample_kernel<<<sgrid, 256>>>(mixed_p, lay_geo + (size_t)i * CH * 6,
                                      lay_box + (size_t)i * CH * 6, x_p, dst, ph, pl);
    }

    pool_kernel<<<BATCH * CH, 256>>>(feat, pool_p);
    dense_kernel<<<(BATCH * NOUT + 255) / 256, 256>>>(pool_p, dense_w, dense_b, logits);
}